// round 15
// baseline (speedup 1.0000x reference)
#include <cuda_runtime.h>
#include <cuda_fp16.h>
#include <math.h>
#include <stdint.h>

// Problem constants
#define Bv   4
#define Tv   4096
#define Dv   1024
#define NWv  64
#define Mv   16384          // B*T token rows
#define K3v  3072
#define NALL 4096

// ---------------- scratch (device globals; no runtime allocation) ----------
__device__ __half g_xh[(size_t)Mv * Dv];
__device__ __half g_wallh[(size_t)NALL * Dv];    // W_qkv rows 0-3071, W_cross 3072-4095
__device__ __half g_wouth[(size_t)Dv * Dv];
__device__ __half g_qkvh[(size_t)Mv * K3v];
__device__ __half g_localh[(size_t)Mv * Dv];
__device__ __half g_csh[256 * Dv];
__device__ float  g_csout[256 * Dv];
__device__ float  g_scores[Mv];
__device__ float  g_sum[Bv * NWv * Dv];

// ---------------------------------------------------------------------------
__device__ __forceinline__ uint32_t smem_u32(const void* p) {
    uint32_t a;
    asm("{ .reg .u64 t; cvta.to.shared.u64 t, %1; cvt.u32.u64 %0, t; }"
        : "=r"(a) : "l"(p));
    return a;
}
#define CP16(dst, src) \
    asm volatile("cp.async.cg.shared.global [%0], [%1], 16;" :: "r"(dst), "l"(src))
#define CPCOMMIT() asm volatile("cp.async.commit_group;" ::: "memory")
#define CPWAIT0()  asm volatile("cp.async.wait_group 0;" ::: "memory")
#define CPWAIT1()  asm volatile("cp.async.wait_group 1;" ::: "memory")

#define LDSM4(r0, r1, r2, r3, addr) \
    asm volatile("ldmatrix.sync.aligned.m8n8.x4.shared.b16 {%0,%1,%2,%3}, [%4];" \
        : "=r"(r0), "=r"(r1), "=r"(r2), "=r"(r3) : "r"(addr))

__device__ __forceinline__ void mma16816(float* d, const uint32_t* a, const uint32_t* b) {
    asm volatile(
        "mma.sync.aligned.m16n8k16.row.col.f32.f16.f16.f32 "
        "{%0,%1,%2,%3}, {%4,%5,%6,%7}, {%8,%9}, {%0,%1,%2,%3};"
        : "+f"(d[0]), "+f"(d[1]), "+f"(d[2]), "+f"(d[3])
        : "r"(a[0]), "r"(a[1]), "r"(a[2]), "r"(a[3]), "r"(b[0]), "r"(b[1]));
}
__device__ __forceinline__ uint32_t packh2(float x, float y) {
    uint32_t r;
    asm("cvt.rn.f16x2.f32 %0, %1, %2;" : "=r"(r) : "f"(y), "f"(x));
    return r;
}

// ---------------------------------------------------------------------------
// ONE conversion kernel: x -> g_xh, W_qkv++W_cross -> g_wallh, W_out -> g_wouth,
// and zero g_scores.  Segment layout over float4 index space.
// ---------------------------------------------------------------------------
#define N4_X    (Mv * Dv / 4)            // 4,194,304
#define N4_WALL (NALL * Dv / 4)          // 1,048,576
#define N4_WOUT (Dv * Dv / 4)            // 262,144
#define N4_ALL  (N4_X + N4_WALL + N4_WOUT)

__global__ void cvt_all_k(const float* __restrict__ x,
                          const float* __restrict__ wqkv,
                          const float* __restrict__ wcross,
                          const float* __restrict__ wout)
{
    const int i = blockIdx.x * blockDim.x + threadIdx.x;
    if (i < N4_X) {
        const float4 v = ((const float4*)x)[i];
        ((__half2*)g_xh)[i * 2]     = __floats2half2_rn(v.x, v.y);
        ((__half2*)g_xh)[i * 2 + 1] = __floats2half2_rn(v.z, v.w);
    } else if (i < N4_X + N4_WALL) {
        const int j = i - N4_X;
        const float4 v = (j < K3v * Dv / 4)
            ? ((const float4*)wqkv)[j]
            : ((const float4*)wcross)[j - K3v * Dv / 4];
        ((__half2*)g_wallh)[j * 2]     = __floats2half2_rn(v.x, v.y);
        ((__half2*)g_wallh)[j * 2 + 1] = __floats2half2_rn(v.z, v.w);
    } else if (i < N4_ALL) {
        const int j = i - N4_X - N4_WALL;
        const float4 v = ((const float4*)wout)[j];
        ((__half2*)g_wouth)[j * 2]     = __floats2half2_rn(v.x, v.y);
        ((__half2*)g_wouth)[j * 2 + 1] = __floats2half2_rn(v.z, v.w);
    }
    if (i < Mv / 4)
        ((float4*)g_scores)[i] = make_float4(0.f, 0.f, 0.f, 0.f);
}

// ---------------------------------------------------------------------------
// fp16 tensor-core GEMM, CTA 128x128, BK=64, 3-stage cp.async, ONE sync/iter,
// cp.async interleaved behind mma (proven R12 inner loop). 2 CTAs/SM.
// MODE 0: half write to g_qkvh (qkv projection).
// MODE 1: plain f32 write.
// MODE 2: f32 + bias + 0.25*g_csout[window].
// MODE 3: cross scores: atomicAdd rowsum tanh(c + bias[col]).
// ---------------------------------------------------------------------------
#define TILEB 18432                     // 128 rows * 144 B
#define BUFB  (2 * TILEB)               // 36864
#define SMEM_GEMM (3 * BUFB)            // 110592

template <int MODE>
__global__ void __launch_bounds__(256, 2)
hgemm(const __half* __restrict__ Ah, const __half* __restrict__ Bh,
      float* __restrict__ Cf, const float* __restrict__ bias, int N)
{
    extern __shared__ __align__(16) char sm[];
    const int tid = threadIdx.x;
    const int w = tid >> 5, l = tid & 31;
    const int row0 = blockIdx.y * 128;
    const int col0 = blockIdx.x * 128;
    const int wm = (w >> 2) * 64;
    const int wn = (w & 3) * 32;

    float acc[4][4][4];
#pragma unroll
    for (int a = 0; a < 4; a++)
#pragma unroll
        for (int b = 0; b < 4; b++)
#pragma unroll
            for (int c = 0; c < 4; c++) acc[a][b][c] = 0.f;

    const uint32_t sb = smem_u32(sm);

    auto issueA = [&](int t, int buf) {
        const __half* Asrc = Ah + (size_t)row0 * Dv + t * 64;
        const uint32_t dA = sb + buf * BUFB;
#pragma unroll
        for (int it = 0; it < 4; it++) {
            const int idx = it * 256 + tid;
            const int m = idx >> 3, kq = idx & 7;
            CP16(dA + m * 144 + kq * 16, Asrc + (size_t)m * Dv + kq * 8);
        }
    };
    auto issueB = [&](int t, int buf) {
        const __half* Bsrc = Bh + (size_t)col0 * Dv + t * 64;
        const uint32_t dB = sb + buf * BUFB + TILEB;
#pragma unroll
        for (int it = 0; it < 4; it++) {
            const int idx = it * 256 + tid;
            const int m = idx >> 3, kq = idx & 7;
            CP16(dB + m * 144 + kq * 16, Bsrc + (size_t)m * Dv + kq * 8);
        }
        CPCOMMIT();
    };

    issueA(0, 0); issueB(0, 0);
    issueA(1, 1); issueB(1, 1);

    uint32_t offA[4], offB[2];
#pragma unroll
    for (int mt = 0; mt < 4; mt++)
        offA[mt] = (uint32_t)(wm + mt * 16 + (l & 15)) * 144 + (l >> 4) * 16;
#pragma unroll
    for (int p = 0; p < 2; p++)
        offB[p] = (uint32_t)(TILEB + (wn + p * 16 + ((l >> 4) << 3) + (l & 7)) * 144
                             + ((l >> 3) & 1) * 16);

    int buf = 0;
    for (int t = 0; t < 16; t++) {
        if (t < 15) CPWAIT1(); else CPWAIT0();
        __syncthreads();

        const uint32_t bb = sb + buf * BUFB;
        int nb = buf + 2; if (nb >= 3) nb -= 3;
        const bool pf = (t + 2 < 16);

#pragma unroll
        for (int kt = 0; kt < 4; kt++) {
            const uint32_t ko = kt * 32;
            uint32_t a[4][4], b[4][2];
#pragma unroll
            for (int mt = 0; mt < 4; mt++)
                LDSM4(a[mt][0], a[mt][1], a[mt][2], a[mt][3], bb + offA[mt] + ko);
#pragma unroll
            for (int p = 0; p < 2; p++)
                LDSM4(b[2 * p][0], b[2 * p][1], b[2 * p + 1][0], b[2 * p + 1][1],
                      bb + offB[p] + ko);
#pragma unroll
            for (int mt = 0; mt < 4; mt++)
#pragma unroll
                for (int nt = 0; nt < 4; nt++)
                    mma16816(acc[mt][nt], a[mt], b[nt]);

            if (kt == 0 && pf) issueA(t + 2, nb);
            if (kt == 1 && pf) issueB(t + 2, nb);
        }
        if (++buf == 3) buf = 0;
    }

    const int rbase = row0 + wm + (l >> 2);
    const int cbase = col0 + wn + (l & 3) * 2;

    if (MODE == 3) {
        // cross scores: rowsum of tanh(c + b_cross[col])
#pragma unroll
        for (int mt = 0; mt < 4; mt++) {
            float s0 = 0.f, s1 = 0.f;
#pragma unroll
            for (int nt = 0; nt < 4; nt++) {
                const int c = cbase + nt * 8;
                const float b0 = bias[c], b1 = bias[c + 1];
                s0 += tanhf(acc[mt][nt][0] + b0) + tanhf(acc[mt][nt][1] + b1);
                s1 += tanhf(acc[mt][nt][2] + b0) + tanhf(acc[mt][nt][3] + b1);
            }
            s0 += __shfl_xor_sync(0xffffffffu, s0, 1);
            s0 += __shfl_xor_sync(0xffffffffu, s0, 2);
            s1 += __shfl_xor_sync(0xffffffffu, s1, 1);
            s1 += __shfl_xor_sync(0xffffffffu, s1, 2);
            if ((l & 3) == 0) {
                atomicAdd(&g_scores[rbase + mt * 16], s0);
                atomicAdd(&g_scores[rbase + mt * 16 + 8], s1);
            }
        }
    } else if (MODE == 0) {
#pragma unroll
        for (int mt = 0; mt < 4; mt++) {
            const int row = rbase + mt * 16;
#pragma unroll
            for (int nt = 0; nt < 4; nt++) {
                const int col = cbase + nt * 8;
                *(__half2*)(g_qkvh + (size_t)row * K3v + col) =
                    __floats2half2_rn(acc[mt][nt][0], acc[mt][nt][1]);
                *(__half2*)(g_qkvh + (size_t)(row + 8) * K3v + col) =
                    __floats2half2_rn(acc[mt][nt][2], acc[mt][nt][3]);
            }
        }
    } else if (MODE == 1) {
#pragma unroll
        for (int mt = 0; mt < 4; mt++) {
            const int row = rbase + mt * 16;
#pragma unroll
            for (int nt = 0; nt < 4; nt++) {
                const int col = cbase + nt * 8;
                *(float2*)(Cf + (size_t)row * N + col) =
                    make_float2(acc[mt][nt][0], acc[mt][nt][1]);
                *(float2*)(Cf + (size_t)(row + 8) * N + col) =
                    make_float2(acc[mt][nt][2], acc[mt][nt][3]);
            }
        }
    } else {
#pragma unroll
        for (int mt = 0; mt < 4; mt++) {
            const int row = rbase + mt * 16;
#pragma unroll
            for (int nt = 0; nt < 4; nt++) {
                const int col = cbase + nt * 8;
                const float2 cs0 = *(const float2*)(g_csout + (size_t)(row >> 6) * Dv + col);
                const float2 cs1 = *(const float2*)(g_csout + (size_t)((row + 8) >> 6) * Dv + col);
                const float b0 = bias[col], b1 = bias[col + 1];
                *(float2*)(Cf + (size_t)row * N + col) =
                    make_float2(acc[mt][nt][0] + b0 + 0.25f * cs0.x,
                                acc[mt][nt][1] + b1 + 0.25f * cs0.y);
                *(float2*)(Cf + (size_t)(row + 8) * N + col) =
                    make_float2(acc[mt][nt][2] + b0 + 0.25f * cs1.x,
                                acc[mt][nt][3] + b1 + 0.25f * cs1.y);
            }
        }
    }
}

// ---------------------------------------------------------------------------
// Tensor-core windowed attention (unchanged, proven since R6).
// ---------------------------------------------------------------------------
__global__ void __launch_bounds__(128)
attn_k()
{
    __shared__ __align__(16) __half sQ[64 * 72];
    __shared__ __align__(16) __half sK[64 * 72];
    __shared__ __align__(16) __half sVt[64 * 72];

    const int blk = blockIdx.x;
    const int n = blk & 63;
    const int h = (blk >> 6) & 15;
    const int b = blk >> 10;
    const int tid = threadIdx.x;
    const int w = tid >> 5, l = tid & 31;

    const __half* base = g_qkvh + ((size_t)(b * Tv + n * 64)) * K3v + h * 64;

#pragma unroll
    for (int j = 0; j < 16; j++) {
        const int idx = j * 128 + tid;
        const int r = idx >> 5, c2 = idx & 31;
        const __half* rp = base + (size_t)r * K3v;
        const __half2 qv = *(const __half2*)(rp + c2 * 2);
        const __half2 kv = *(const __half2*)(rp + Dv + c2 * 2);
        const __half2 vv = *(const __half2*)(rp + 2 * Dv + c2 * 2);
        *(__half2*)&sQ[r * 72 + c2 * 2] = qv;
        *(__half2*)&sK[r * 72 + c2 * 2] = kv;
        sVt[(c2 * 2) * 72 + r]     = __low2half(vv);
        sVt[(c2 * 2 + 1) * 72 + r] = __high2half(vv);
    }
    __syncthreads();

    const int gr = l >> 2;
    const int gc = (l & 3) * 2;

    float sacc[8][4];
#pragma unroll
    for (int nt = 0; nt < 8; nt++)
#pragma unroll
        for (int c = 0; c < 4; c++) sacc[nt][c] = 0.f;

#pragma unroll
    for (int kt = 0; kt < 4; kt++) {
        uint32_t a[4];
        const __half* qp = sQ + (w * 16 + gr) * 72 + kt * 16 + gc;
        a[0] = *(const uint32_t*)(qp);
        a[1] = *(const uint32_t*)(qp + 8 * 72);
        a[2] = *(const uint32_t*)(qp + 8);
        a[3] = *(const uint32_t*)(qp + 8 * 72 + 8);
#pragma unroll
        for (int nt = 0; nt < 8; nt++) {
            uint32_t bb[2];
            const __half* kp = sK + (nt * 8 + gr) * 72 + kt * 16 + gc;
            bb[0] = *(const uint32_t*)(kp);
            bb[1] = *(const uint32_t*)(kp + 8);
            mma16816(sacc[nt], a, bb);
        }
    }

    float m0 = -1e30f, m1 = -1e30f;
#pragma unroll
    for (int nt = 0; nt < 8; nt++) {
#pragma unroll
        for (int c = 0; c < 4; c++) sacc[nt][c] *= 0.125f;
        m0 = fmaxf(m0, fmaxf(sacc[nt][0], sacc[nt][1]));
        m1 = fmaxf(m1, fmaxf(sacc[nt][2], sacc[nt][3]));
    }
    m0 = fmaxf(m0, __shfl_xor_sync(0xffffffffu, m0, 1));
    m0 = fmaxf(m0, __shfl_xor_sync(0xffffffffu, m0, 2));
    m1 = fmaxf(m1, __shfl_xor_sync(0xffffffffu, m1, 1));
    m1 = fmaxf(m1, __shfl_xor_sync(0xffffffffu, m1, 2));

    float s0 = 0.f, s1 = 0.f;
#pragma unroll
    for (int nt = 0; nt < 8; nt++) {
        sacc[nt][0] = __expf(sacc[nt][0] - m0);
        sacc[nt][1] = __expf(sacc[nt][1] - m0);
        sacc[nt][2] = __expf(sacc[nt][2] - m1);
        sacc[nt][3] = __expf(sacc[nt][3] - m1);
        s0 += sacc[nt][0] + sacc[nt][1];
        s1 += sacc[nt][2] + sacc[nt][3];
    }
    s0 += __shfl_xor_sync(0xffffffffu, s0, 1);
    s0 += __shfl_xor_sync(0xffffffffu, s0, 2);
    s1 += __shfl_xor_sync(0xffffffffu, s1, 1);
    s1 += __shfl_xor_sync(0xffffffffu, s1, 2);
    const float i0 = 1.f / s0, i1 = 1.f / s1;
#pragma unroll
    for (int nt = 0; nt < 8; nt++) {
        sacc[nt][0] *= i0; sacc[nt][1] *= i0;
        sacc[nt][2] *= i1; sacc[nt][3] *= i1;
    }

    float oacc[8][4];
#pragma unroll
    for (int nt = 0; nt < 8; nt++)
#pragma unroll
        for (int c = 0; c < 4; c++) oacc[nt][c] = 0.f;

#pragma unroll
    for (int kt = 0; kt < 4; kt++) {
        uint32_t a[4];
        a[0] = packh2(sacc[2 * kt][0],     sacc[2 * kt][1]);
        a[1] = packh2(sacc[2 * kt][2],     sacc[2 * kt][3]);
        a[2] = packh2(sacc[2 * kt + 1][0], sacc[2 * kt + 1][1]);
        a[3] = packh2(sacc[2 * kt + 1][2], sacc[2 * kt + 1][3]);
#pragma unroll
        for (int nt = 0; nt < 8; nt++) {
            uint32_t bb[2];
            const __half* vp = sVt + (nt * 8 + gr) * 72 + kt * 16 + gc;
            bb[0] = *(const uint32_t*)(vp);
            bb[1] = *(const uint32_t*)(vp + 8);
            mma16816(oacc[nt], a, bb);
        }
    }

    __half* op = g_localh + ((size_t)(b * Tv + n * 64)) * Dv + h * 64;
    const int orow = w * 16 + gr;
#pragma unroll
    for (int nt = 0; nt < 8; nt++) {
        const int col = nt * 8 + gc;
        *(__half2*)(op + (size_t)orow * Dv + col) =
            __floats2half2_rn(oacc[nt][0], oacc[nt][1]);
        *(__half2*)(op + (size_t)(orow + 8) * Dv + col) =
            __floats2half2_rn(oacc[nt][2], oacc[nt][3]);
    }
}

// ---------------------------------------------------------------------------
__global__ void __launch_bounds__(256)
summary_k()
{
    __shared__ float wsh[64];
    const int blk = blockIdx.x;
    const int base = blk * 64;
    const int tid = threadIdx.x;

    if (tid < 64) wsh[tid] = g_scores[base + tid] * (1.0f / 1024.0f);
    __syncthreads();

    float mx = -1e30f;
    for (int w = 0; w < 64; w++) mx = fmaxf(mx, wsh[w]);
    float sum = 0.f;
    for (int w = 0; w < 64; w++) sum += __expf(wsh[w] - mx);
    __syncthreads();
    if (tid < 64) wsh[tid] = __expf(wsh[tid] - mx) / sum;
    __syncthreads();

    for (int d = tid; d < Dv; d += 256) {
        float acc = 0.f;
        const __half* xp = g_xh + (size_t)base * Dv + d;
#pragma unroll 8
        for (int w = 0; w < 64; w++)
            acc += wsh[w] * __half2float(xp[(size_t)w * Dv]);
        g_sum[(size_t)blk * Dv + d] = acc;
    }
}

__global__ void __launch_bounds__(256)
cs_k(const int* __restrict__ jitter)
{
    __shared__ float lg[64];
    __shared__ float p[64];
    __shared__ int jit[64];
    const int blk = blockIdx.x;
    const int b = blk >> 6;
    const int tid = threadIdx.x;

    if (tid < 64) jit[tid] = jitter[tid];
    __syncthreads();

    const float* srow = g_sum + (size_t)blk * Dv;
    const int wid = tid >> 5, lane = tid & 31;
    for (int m8 = 0; m8 < 8; m8++) {
        const int m = wid * 8 + m8;
        const float* jrow = g_sum + (size_t)(b * 64 + jit[m]) * Dv;
        float a = 0.f;
        for (int d = lane; d < Dv; d += 32) a += srow[d] * jrow[d];
#pragma unroll
        for (int off = 16; off; off >>= 1) a += __shfl_xor_sync(0xffffffffu, a, off);
        if (lane == 0) lg[m] = a * (1.0f / 32.0f);
    }
    __syncthreads();

    float mx = -1e30f;
    for (int m = 0; m < 64; m++) mx = fmaxf(mx, lg[m]);
    float sum = 0.f;
    for (int m = 0; m < 64; m++) sum += __expf(lg[m] - mx);
    __syncthreads();
    if (tid < 64) p[tid] = __expf(lg[tid] - mx) / sum;
    __syncthreads();

    for (int d = tid; d < Dv; d += 256) {
        float acc = 0.f;
#pragma unroll 8
        for (int m = 0; m < 64; m++)
            acc += p[m] * g_sum[(size_t)(b * 64 + jit[m]) * Dv + d];
        g_csh[(size_t)blk * Dv + d] = __float2half(acc);
    }
}

// ---------------------------------------------------------------------------
extern "C" void kernel_launch(void* const* d_in, const int* in_sizes, int n_in,
                              void* d_out, int out_size)
{
    const float* x       = (const float*)d_in[0];
    const float* W_qkv   = (const float*)d_in[1];
    const float* W_out   = (const float*)d_in[2];
    const float* b_out   = (const float*)d_in[3];
    const float* W_cross = (const float*)d_in[4];
    const float* b_cross = (const float*)d_in[5];
    const int*   jitter  = (const int*)d_in[6];
    float* out = (float*)d_out;

    cudaFuncSetAttribute(hgemm<0>, cudaFuncAttributeMaxDynamicSharedMemorySize, SMEM_GEMM);
    cudaFuncSetAttribute(hgemm<1>, cudaFuncAttributeMaxDynamicSharedMemorySize, SMEM_GEMM);
    cudaFuncSetAttribute(hgemm<2>, cudaFuncAttributeMaxDynamicSharedMemorySize, SMEM_GEMM);
    cudaFuncSetAttribute(hgemm<3>, cudaFuncAttributeMaxDynamicSharedMemorySize, SMEM_GEMM);

    __half *xh, *wallh, *wouth, *localh, *csh;
    float* csout;
    cudaGetSymbolAddress((void**)&xh, g_xh);
    cudaGetSymbolAddress((void**)&wallh, g_wallh);
    cudaGetSymbolAddress((void**)&wouth, g_wouth);
    cudaGetSymbolAddress((void**)&localh, g_localh);
    cudaGetSymbolAddress((void**)&csh, g_csh);
    cudaGetSymbolAddress((void**)&csout, g_csout);

    struct Res {
        cudaStream_t sB;
        cudaEvent_t evCvt, evJoin;
        Res() {
            cudaStreamCreateWithFlags(&sB, cudaStreamNonBlocking);
            cudaEventCreateWithFlags(&evCvt, cudaEventDisableTiming);
            cudaEventCreateWithFlags(&evJoin, cudaEventDisableTiming);
        }
    };
    static Res R;

    // ---- single conversion kernel (x, W_qkv++W_cross, W_out, zero scores)
    cvt_all_k<<<(N4_ALL + 255) / 256, 256>>>(x, W_qkv, W_cross, W_out);
    cudaEventRecord(R.evCvt, 0);

    // ---- chain B (side stream): cross scores -> summaries -> cs -> csout
    cudaStreamWaitEvent(R.sB, R.evCvt, 0);
    hgemm<3><<<dim3(8, 128), 256, SMEM_GEMM, R.sB>>>(xh, wallh + (size_t)K3v * Dv,
                                                     nullptr, b_cross, 0);
    summary_k<<<Bv * NWv, 256, 0, R.sB>>>();
    cs_k<<<Bv * NWv, 256, 0, R.sB>>>(jitter);
    hgemm<1><<<dim3(8, 2), 256, SMEM_GEMM, R.sB>>>(csh, wouth, csout, nullptr, Dv);
    cudaEventRecord(R.evJoin, R.sB);

    // ---- chain A (main stream): qkv GEMM -> windowed attention
    hgemm<0><<<dim3(24, 128), 256, SMEM_GEMM>>>(xh, wallh, nullptr, nullptr, 0);
    attn_k<<<Bv * 16 * NWv, 128>>>();

    // ---- join, then final projection with fused bias + 0.25*csout
    cudaStreamWaitEvent(0, R.evJoin, 0);
    hgemm<2><<<dim3(8, 128), 256, SMEM_GEMM>>>(localh, wouth, out, b_out, Dv);
}

// round 16
// speedup vs baseline: 1.0566x; 1.0566x over previous
#include <cuda_runtime.h>
#include <cuda_fp16.h>
#include <math.h>
#include <stdint.h>

// Problem constants
#define Bv   4
#define Tv   4096
#define Dv   1024
#define NWv  64
#define Mv   16384          // B*T token rows
#define K3v  3072
#define NALL 4096           // qkv (3072) + cross (1024) fused N

// ---------------- scratch (device globals; no runtime allocation) ----------
__device__ __half g_xh[(size_t)Mv * Dv];
__device__ __half g_wallh[(size_t)NALL * Dv];    // W_qkv rows 0-3071, W_cross 3072-4095
__device__ __half g_wouth[(size_t)Dv * Dv];
__device__ __half g_qkvh[(size_t)Mv * K3v];
__device__ __half g_localh[(size_t)Mv * Dv];
__device__ __half g_csh[256 * Dv];
__device__ float  g_csout[256 * Dv];
__device__ float  g_scores[Mv];
__device__ float  g_sum[Bv * NWv * Dv];

// ---------------------------------------------------------------------------
__device__ __forceinline__ uint32_t smem_u32(const void* p) {
    uint32_t a;
    asm("{ .reg .u64 t; cvta.to.shared.u64 t, %1; cvt.u32.u64 %0, t; }"
        : "=r"(a) : "l"(p));
    return a;
}
#define CP16(dst, src) \
    asm volatile("cp.async.cg.shared.global [%0], [%1], 16;" :: "r"(dst), "l"(src))
#define CPCOMMIT() asm volatile("cp.async.commit_group;" ::: "memory")
#define CPWAIT0()  asm volatile("cp.async.wait_group 0;" ::: "memory")
#define CPWAIT1()  asm volatile("cp.async.wait_group 1;" ::: "memory")

#define LDSM4(r0, r1, r2, r3, addr) \
    asm volatile("ldmatrix.sync.aligned.m8n8.x4.shared.b16 {%0,%1,%2,%3}, [%4];" \
        : "=r"(r0), "=r"(r1), "=r"(r2), "=r"(r3) : "r"(addr))

__device__ __forceinline__ void mma16816(float* d, const uint32_t* a, const uint32_t* b) {
    asm volatile(
        "mma.sync.aligned.m16n8k16.row.col.f32.f16.f16.f32 "
        "{%0,%1,%2,%3}, {%4,%5,%6,%7}, {%8,%9}, {%0,%1,%2,%3};"
        : "+f"(d[0]), "+f"(d[1]), "+f"(d[2]), "+f"(d[3])
        : "r"(a[0]), "r"(a[1]), "r"(a[2]), "r"(a[3]), "r"(b[0]), "r"(b[1]));
}
__device__ __forceinline__ uint32_t packh2(float x, float y) {
    uint32_t r;
    asm("cvt.rn.f16x2.f32 %0, %1, %2;" : "=r"(r) : "f"(y), "f"(x));
    return r;
}

// ---------------------------------------------------------------------------
// ONE conversion kernel: x -> g_xh, W_qkv++W_cross -> g_wallh, W_out -> g_wouth,
// and zero g_scores.
// ---------------------------------------------------------------------------
#define N4_X    (Mv * Dv / 4)
#define N4_WALL (NALL * Dv / 4)
#define N4_WOUT (Dv * Dv / 4)
#define N4_ALL  (N4_X + N4_WALL + N4_WOUT)

__global__ void cvt_all_k(const float* __restrict__ x,
                          const float* __restrict__ wqkv,
                          const float* __restrict__ wcross,
                          const float* __restrict__ wout)
{
    const int i = blockIdx.x * blockDim.x + threadIdx.x;
    if (i < N4_X) {
        const float4 v = ((const float4*)x)[i];
        ((__half2*)g_xh)[i * 2]     = __floats2half2_rn(v.x, v.y);
        ((__half2*)g_xh)[i * 2 + 1] = __floats2half2_rn(v.z, v.w);
    } else if (i < N4_X + N4_WALL) {
        const int j = i - N4_X;
        const float4 v = (j < K3v * Dv / 4)
            ? ((const float4*)wqkv)[j]
            : ((const float4*)wcross)[j - K3v * Dv / 4];
        ((__half2*)g_wallh)[j * 2]     = __floats2half2_rn(v.x, v.y);
        ((__half2*)g_wallh)[j * 2 + 1] = __floats2half2_rn(v.z, v.w);
    } else if (i < N4_ALL) {
        const int j = i - N4_X - N4_WALL;
        const float4 v = ((const float4*)wout)[j];
        ((__half2*)g_wouth)[j * 2]     = __floats2half2_rn(v.x, v.y);
        ((__half2*)g_wouth)[j * 2 + 1] = __floats2half2_rn(v.z, v.w);
    }
    if (i < Mv / 4)
        ((float4*)g_scores)[i] = make_float4(0.f, 0.f, 0.f, 0.f);
}

// ---------------------------------------------------------------------------
// fp16 tensor-core GEMM, CTA 128x128, BK=64, 3-stage cp.async, ONE sync/iter,
// cp.async interleaved behind mma (champion R12 inner loop). 2 CTAs/SM.
// MODE 0 (wall): col0 < 3072 -> half write g_qkvh; col0 >= 3072 -> tanh
//                rowsum scores (atomicAdd).
// MODE 1: plain f32 write. MODE 2: f32 + bias + 0.25*g_csout[window].
// ---------------------------------------------------------------------------
#define TILEB 18432                     // 128 rows * 144 B
#define BUFB  (2 * TILEB)               // 36864
#define SMEM_GEMM (3 * BUFB)            // 110592

template <int MODE>
__global__ void __launch_bounds__(256, 2)
hgemm(const __half* __restrict__ Ah, const __half* __restrict__ Bh,
      float* __restrict__ Cf, const float* __restrict__ bias, int N)
{
    extern __shared__ __align__(16) char sm[];
    const int tid = threadIdx.x;
    const int w = tid >> 5, l = tid & 31;
    const int row0 = blockIdx.y * 128;
    const int col0 = blockIdx.x * 128;
    const int wm = (w >> 2) * 64;
    const int wn = (w & 3) * 32;

    float acc[4][4][4];
#pragma unroll
    for (int a = 0; a < 4; a++)
#pragma unroll
        for (int b = 0; b < 4; b++)
#pragma unroll
            for (int c = 0; c < 4; c++) acc[a][b][c] = 0.f;

    const uint32_t sb = smem_u32(sm);

    auto issueA = [&](int t, int buf) {
        const __half* Asrc = Ah + (size_t)row0 * Dv + t * 64;
        const uint32_t dA = sb + buf * BUFB;
#pragma unroll
        for (int it = 0; it < 4; it++) {
            const int idx = it * 256 + tid;
            const int m = idx >> 3, kq = idx & 7;
            CP16(dA + m * 144 + kq * 16, Asrc + (size_t)m * Dv + kq * 8);
        }
    };
    auto issueB = [&](int t, int buf) {
        const __half* Bsrc = Bh + (size_t)col0 * Dv + t * 64;
        const uint32_t dB = sb + buf * BUFB + TILEB;
#pragma unroll
        for (int it = 0; it < 4; it++) {
            const int idx = it * 256 + tid;
            const int m = idx >> 3, kq = idx & 7;
            CP16(dB + m * 144 + kq * 16, Bsrc + (size_t)m * Dv + kq * 8);
        }
        CPCOMMIT();
    };

    issueA(0, 0); issueB(0, 0);
    issueA(1, 1); issueB(1, 1);

    uint32_t offA[4], offB[2];
#pragma unroll
    for (int mt = 0; mt < 4; mt++)
        offA[mt] = (uint32_t)(wm + mt * 16 + (l & 15)) * 144 + (l >> 4) * 16;
#pragma unroll
    for (int p = 0; p < 2; p++)
        offB[p] = (uint32_t)(TILEB + (wn + p * 16 + ((l >> 4) << 3) + (l & 7)) * 144
                             + ((l >> 3) & 1) * 16);

    int buf = 0;                        // t % 3
    for (int t = 0; t < 16; t++) {
        if (t < 15) CPWAIT1(); else CPWAIT0();
        __syncthreads();                // stage t resident; iter t-1 reads done

        const uint32_t bb = sb + buf * BUFB;
        int nb = buf + 2; if (nb >= 3) nb -= 3;
        const bool pf = (t + 2 < 16);

#pragma unroll
        for (int kt = 0; kt < 4; kt++) {
            const uint32_t ko = kt * 32;
            uint32_t a[4][4], b[4][2];
#pragma unroll
            for (int mt = 0; mt < 4; mt++)
                LDSM4(a[mt][0], a[mt][1], a[mt][2], a[mt][3], bb + offA[mt] + ko);
#pragma unroll
            for (int p = 0; p < 2; p++)
                LDSM4(b[2 * p][0], b[2 * p][1], b[2 * p + 1][0], b[2 * p + 1][1],
                      bb + offB[p] + ko);
#pragma unroll
            for (int mt = 0; mt < 4; mt++)
#pragma unroll
                for (int nt = 0; nt < 4; nt++)
                    mma16816(acc[mt][nt], a[mt], b[nt]);

            if (kt == 0 && pf) issueA(t + 2, nb);   // hide LSU behind mma
            if (kt == 1 && pf) issueB(t + 2, nb);
        }
        if (++buf == 3) buf = 0;
    }

    const int rbase = row0 + wm + (l >> 2);
    const int cbase = col0 + wn + (l & 3) * 2;

    if (MODE == 0 && col0 >= K3v) {
#pragma unroll
        for (int mt = 0; mt < 4; mt++) {
            float s0 = 0.f, s1 = 0.f;
#pragma unroll
            for (int nt = 0; nt < 4; nt++) {
                const int c = cbase + nt * 8 - K3v;
                const float b0 = bias[c], b1 = bias[c + 1];
                s0 += tanhf(acc[mt][nt][0] + b0) + tanhf(acc[mt][nt][1] + b1);
                s1 += tanhf(acc[mt][nt][2] + b0) + tanhf(acc[mt][nt][3] + b1);
            }
            s0 += __shfl_xor_sync(0xffffffffu, s0, 1);
            s0 += __shfl_xor_sync(0xffffffffu, s0, 2);
            s1 += __shfl_xor_sync(0xffffffffu, s1, 1);
            s1 += __shfl_xor_sync(0xffffffffu, s1, 2);
            if ((l & 3) == 0) {
                atomicAdd(&g_scores[rbase + mt * 16], s0);
                atomicAdd(&g_scores[rbase + mt * 16 + 8], s1);
            }
        }
    } else if (MODE == 0) {
#pragma unroll
        for (int mt = 0; mt < 4; mt++) {
            const int row = rbase + mt * 16;
#pragma unroll
            for (int nt = 0; nt < 4; nt++) {
                const int col = cbase + nt * 8;
                *(__half2*)(g_qkvh + (size_t)row * K3v + col) =
                    __floats2half2_rn(acc[mt][nt][0], acc[mt][nt][1]);
                *(__half2*)(g_qkvh + (size_t)(row + 8) * K3v + col) =
                    __floats2half2_rn(acc[mt][nt][2], acc[mt][nt][3]);
            }
        }
    } else if (MODE == 1) {
#pragma unroll
        for (int mt = 0; mt < 4; mt++) {
            const int row = rbase + mt * 16;
#pragma unroll
            for (int nt = 0; nt < 4; nt++) {
                const int col = cbase + nt * 8;
                *(float2*)(Cf + (size_t)row * N + col) =
                    make_float2(acc[mt][nt][0], acc[mt][nt][1]);
                *(float2*)(Cf + (size_t)(row + 8) * N + col) =
                    make_float2(acc[mt][nt][2], acc[mt][nt][3]);
            }
        }
    } else {
#pragma unroll
        for (int mt = 0; mt < 4; mt++) {
            const int row = rbase + mt * 16;
#pragma unroll
            for (int nt = 0; nt < 4; nt++) {
                const int col = cbase + nt * 8;
                const float2 cs0 = *(const float2*)(g_csout + (size_t)(row >> 6) * Dv + col);
                const float2 cs1 = *(const float2*)(g_csout + (size_t)((row + 8) >> 6) * Dv + col);
                const float b0 = bias[col], b1 = bias[col + 1];
                *(float2*)(Cf + (size_t)row * N + col) =
                    make_float2(acc[mt][nt][0] + b0 + 0.25f * cs0.x,
                                acc[mt][nt][1] + b1 + 0.25f * cs0.y);
                *(float2*)(Cf + (size_t)(row + 8) * N + col) =
                    make_float2(acc[mt][nt][2] + b0 + 0.25f * cs1.x,
                                acc[mt][nt][3] + b1 + 0.25f * cs1.y);
            }
        }
    }
}

// ---------------------------------------------------------------------------
// Tensor-core windowed attention (unchanged, proven since R6).
// ---------------------------------------------------------------------------
__global__ void __launch_bounds__(128)
attn_k()
{
    __shared__ __align__(16) __half sQ[64 * 72];
    __shared__ __align__(16) __half sK[64 * 72];
    __shared__ __align__(16) __half sVt[64 * 72];

    const int blk = blockIdx.x;
    const int n = blk & 63;
    const int h = (blk >> 6) & 15;
    const int b = blk >> 10;
    const int tid = threadIdx.x;
    const int w = tid >> 5, l = tid & 31;

    const __half* base = g_qkvh + ((size_t)(b * Tv + n * 64)) * K3v + h * 64;

#pragma unroll
    for (int j = 0; j < 16; j++) {
        const int idx = j * 128 + tid;
        const int r = idx >> 5, c2 = idx & 31;
        const __half* rp = base + (size_t)r * K3v;
        const __half2 qv = *(const __half2*)(rp + c2 * 2);
        const __half2 kv = *(const __half2*)(rp + Dv + c2 * 2);
        const __half2 vv = *(const __half2*)(rp + 2 * Dv + c2 * 2);
        *(__half2*)&sQ[r * 72 + c2 * 2] = qv;
        *(__half2*)&sK[r * 72 + c2 * 2] = kv;
        sVt[(c2 * 2) * 72 + r]     = __low2half(vv);
        sVt[(c2 * 2 + 1) * 72 + r] = __high2half(vv);
    }
    __syncthreads();

    const int gr = l >> 2;
    const int gc = (l & 3) * 2;

    float sacc[8][4];
#pragma unroll
    for (int nt = 0; nt < 8; nt++)
#pragma unroll
        for (int c = 0; c < 4; c++) sacc[nt][c] = 0.f;

#pragma unroll
    for (int kt = 0; kt < 4; kt++) {
        uint32_t a[4];
        const __half* qp = sQ + (w * 16 + gr) * 72 + kt * 16 + gc;
        a[0] = *(const uint32_t*)(qp);
        a[1] = *(const uint32_t*)(qp + 8 * 72);
        a[2] = *(const uint32_t*)(qp + 8);
        a[3] = *(const uint32_t*)(qp + 8 * 72 + 8);
#pragma unroll
        for (int nt = 0; nt < 8; nt++) {
            uint32_t bb[2];
            const __half* kp = sK + (nt * 8 + gr) * 72 + kt * 16 + gc;
            bb[0] = *(const uint32_t*)(kp);
            bb[1] = *(const uint32_t*)(kp + 8);
            mma16816(sacc[nt], a, bb);
        }
    }

    float m0 = -1e30f, m1 = -1e30f;
#pragma unroll
    for (int nt = 0; nt < 8; nt++) {
#pragma unroll
        for (int c = 0; c < 4; c++) sacc[nt][c] *= 0.125f;
        m0 = fmaxf(m0, fmaxf(sacc[nt][0], sacc[nt][1]));
        m1 = fmaxf(m1, fmaxf(sacc[nt][2], sacc[nt][3]));
    }
    m0 = fmaxf(m0, __shfl_xor_sync(0xffffffffu, m0, 1));
    m0 = fmaxf(m0, __shfl_xor_sync(0xffffffffu, m0, 2));
    m1 = fmaxf(m1, __shfl_xor_sync(0xffffffffu, m1, 1));
    m1 = fmaxf(m1, __shfl_xor_sync(0xffffffffu, m1, 2));

    float s0 = 0.f, s1 = 0.f;
#pragma unroll
    for (int nt = 0; nt < 8; nt++) {
        sacc[nt][0] = __expf(sacc[nt][0] - m0);
        sacc[nt][1] = __expf(sacc[nt][1] - m0);
        sacc[nt][2] = __expf(sacc[nt][2] - m1);
        sacc[nt][3] = __expf(sacc[nt][3] - m1);
        s0 += sacc[nt][0] + sacc[nt][1];
        s1 += sacc[nt][2] + sacc[nt][3];
    }
    s0 += __shfl_xor_sync(0xffffffffu, s0, 1);
    s0 += __shfl_xor_sync(0xffffffffu, s0, 2);
    s1 += __shfl_xor_sync(0xffffffffu, s1, 1);
    s1 += __shfl_xor_sync(0xffffffffu, s1, 2);
    const float i0 = 1.f / s0, i1 = 1.f / s1;
#pragma unroll
    for (int nt = 0; nt < 8; nt++) {
        sacc[nt][0] *= i0; sacc[nt][1] *= i0;
        sacc[nt][2] *= i1; sacc[nt][3] *= i1;
    }

    float oacc[8][4];
#pragma unroll
    for (int nt = 0; nt < 8; nt++)
#pragma unroll
        for (int c = 0; c < 4; c++) oacc[nt][c] = 0.f;

#pragma unroll
    for (int kt = 0; kt < 4; kt++) {
        uint32_t a[4];
        a[0] = packh2(sacc[2 * kt][0],     sacc[2 * kt][1]);
        a[1] = packh2(sacc[2 * kt][2],     sacc[2 * kt][3]);
        a[2] = packh2(sacc[2 * kt + 1][0], sacc[2 * kt + 1][1]);
        a[3] = packh2(sacc[2 * kt + 1][2], sacc[2 * kt + 1][3]);
#pragma unroll
        for (int nt = 0; nt < 8; nt++) {
            uint32_t bb[2];
            const __half* vp = sVt + (nt * 8 + gr) * 72 + kt * 16 + gc;
            bb[0] = *(const uint32_t*)(vp);
            bb[1] = *(const uint32_t*)(vp + 8);
            mma16816(oacc[nt], a, bb);
        }
    }

    __half* op = g_localh + ((size_t)(b * Tv + n * 64)) * Dv + h * 64;
    const int orow = w * 16 + gr;
#pragma unroll
    for (int nt = 0; nt < 8; nt++) {
        const int col = nt * 8 + gc;
        *(__half2*)(op + (size_t)orow * Dv + col) =
            __floats2half2_rn(oacc[nt][0], oacc[nt][1]);
        *(__half2*)(op + (size_t)(orow + 8) * Dv + col) =
            __floats2half2_rn(oacc[nt][2], oacc[nt][3]);
    }
}

// ---------------------------------------------------------------------------
__global__ void __launch_bounds__(256)
summary_k()
{
    __shared__ float wsh[64];
    const int blk = blockIdx.x;
    const int base = blk * 64;
    const int tid = threadIdx.x;

    if (tid < 64) wsh[tid] = g_scores[base + tid] * (1.0f / 1024.0f);
    __syncthreads();

    float mx = -1e30f;
    for (int w = 0; w < 64; w++) mx = fmaxf(mx, wsh[w]);
    float sum = 0.f;
    for (int w = 0; w < 64; w++) sum += __expf(wsh[w] - mx);
    __syncthreads();
    if (tid < 64) wsh[tid] = __expf(wsh[tid] - mx) / sum;
    __syncthreads();

    for (int d = tid; d < Dv; d += 256) {
        float acc = 0.f;
        const __half* xp = g_xh + (size_t)base * Dv + d;
#pragma unroll 8
        for (int w = 0; w < 64; w++)
            acc += wsh[w] * __half2float(xp[(size_t)w * Dv]);
        g_sum[(size_t)blk * Dv + d] = acc;
    }
}

__global__ void __launch_bounds__(256)
cs_k(const int* __restrict__ jitter)
{
    __shared__ float lg[64];
    __shared__ float p[64];
    __shared__ int jit[64];
    const int blk = blockIdx.x;
    const int b = blk >> 6;
    const int tid = threadIdx.x;

    if (tid < 64) jit[tid] = jitter[tid];
    __syncthreads();

    const float* srow = g_sum + (size_t)blk * Dv;
    const int wid = tid >> 5, lane = tid & 31;
    for (int m8 = 0; m8 < 8; m8++) {
        const int m = wid * 8 + m8;
        const float* jrow = g_sum + (size_t)(b * 64 + jit[m]) * Dv;
        float a = 0.f;
        for (int d = lane; d < Dv; d += 32) a += srow[d] * jrow[d];
#pragma unroll
        for (int off = 16; off; off >>= 1) a += __shfl_xor_sync(0xffffffffu, a, off);
        if (lane == 0) lg[m] = a * (1.0f / 32.0f);
    }
    __syncthreads();

    float mx = -1e30f;
    for (int m = 0; m < 64; m++) mx = fmaxf(mx, lg[m]);
    float sum = 0.f;
    for (int m = 0; m < 64; m++) sum += __expf(lg[m] - mx);
    __syncthreads();
    if (tid < 64) p[tid] = __expf(lg[tid] - mx) / sum;
    __syncthreads();

    for (int d = tid; d < Dv; d += 256) {
        float acc = 0.f;
#pragma unroll 8
        for (int m = 0; m < 64; m++)
            acc += p[m] * g_sum[(size_t)(b * 64 + jit[m]) * Dv + d];
        g_csh[(size_t)blk * Dv + d] = __float2half(acc);
    }
}

// ---------------------------------------------------------------------------
extern "C" void kernel_launch(void* const* d_in, const int* in_sizes, int n_in,
                              void* d_out, int out_size)
{
    const float* x       = (const float*)d_in[0];
    const float* W_qkv   = (const float*)d_in[1];
    const float* W_out   = (const float*)d_in[2];
    const float* b_out   = (const float*)d_in[3];
    const float* W_cross = (const float*)d_in[4];
    const float* b_cross = (const float*)d_in[5];
    const int*   jitter  = (const int*)d_in[6];
    float* out = (float*)d_out;

    cudaFuncSetAttribute(hgemm<0>, cudaFuncAttributeMaxDynamicSharedMemorySize, SMEM_GEMM);
    cudaFuncSetAttribute(hgemm<1>, cudaFuncAttributeMaxDynamicSharedMemorySize, SMEM_GEMM);
    cudaFuncSetAttribute(hgemm<2>, cudaFuncAttributeMaxDynamicSharedMemorySize, SMEM_GEMM);

    __half *xh, *wallh, *wouth, *localh, *csh;
    float* csout;
    cudaGetSymbolAddress((void**)&xh, g_xh);
    cudaGetSymbolAddress((void**)&wallh, g_wallh);
    cudaGetSymbolAddress((void**)&wouth, g_wouth);
    cudaGetSymbolAddress((void**)&localh, g_localh);
    cudaGetSymbolAddress((void**)&csh, g_csh);
    cudaGetSymbolAddress((void**)&csout, g_csout);

    struct Res {
        cudaStream_t sB;
        cudaEvent_t evGemm, evJoin;
        Res() {
            cudaStreamCreateWithFlags(&sB, cudaStreamNonBlocking);
            cudaEventCreateWithFlags(&evGemm, cudaEventDisableTiming);
            cudaEventCreateWithFlags(&evJoin, cudaEventDisableTiming);
        }
    };
    static Res R;

    // ---- single conversion kernel (x, W_qkv++W_cross, W_out, zero scores)
    cvt_all_k<<<(N4_ALL + 255) / 256, 256>>>(x, W_qkv, W_cross, W_out);

    // ---- wall GEMM: qkv + cross scores in ONE launch (N = 4096)
    hgemm<0><<<dim3(32, 128), 256, SMEM_GEMM>>>(xh, wallh, nullptr, b_cross, 0);
    cudaEventRecord(R.evGemm, 0);

    // ---- chain B (side stream): summaries -> cs -> csout GEMM
    cudaStreamWaitEvent(R.sB, R.evGemm, 0);
    summary_k<<<Bv * NWv, 256, 0, R.sB>>>();
    cs_k<<<Bv * NWv, 256, 0, R.sB>>>(jitter);
    hgemm<1><<<dim3(8, 2), 256, SMEM_GEMM, R.sB>>>(csh, wouth, csout, nullptr, Dv);
    cudaEventRecord(R.evJoin, R.sB);

    // ---- chain A (main stream): windowed attention
    attn_k<<<Bv * 16 * NWv, 128>>>();

    // ---- join, then final projection with fused bias + 0.25*csout
    cudaStreamWaitEvent(0, R.evJoin, 0);
    hgemm<2><<<dim3(8, 128), 256, SMEM_GEMM>>>(localh, wouth, out, b_out, Dv);
}